// round 3
// baseline (speedup 1.0000x reference)
#include <cuda_runtime.h>
#include <cstdint>

// ---------------- problem constants ----------------
#define BATCH    8192
#define DIMV     1024
#define KTOT     2048          // dimIn + dimOut
#define MT       128           // CTA M tile
#define NTG      32            // per-gate N per CTA (effective N tile = 4*32 = 128)
#define NTILES   (DIMV / NTG)  // 32
#define MTILES   (BATCH / MT)  // 64
#define NTHREADS 256
#define KC       32            // K per pipeline stage
#define NCHUNK   (KTOT / KC)   // 64
#define STAGES   3

// smem pitches (in floats) chosen for conflict-free fragment LDS
#define APITCH   36            // bank = (4*(lane>>2)+(lane&3)) -> 32 distinct
#define BPITCH   136           // bank = (8*(lane&3)+(lane>>2)) -> 32 distinct
#define A_FLOATS (MT * APITCH)             // 4608
#define B_FLOATS (KC * BPITCH)             // 4352
#define STAGE_FLOATS (A_FLOATS + B_FLOATS) // 8960 (mult of 32 -> banks preserved)
#define SM_BIAS_F (STAGES * STAGE_FLOATS)  // 26880 floats
#define SMEM_TOTAL ((SM_BIAS_F + 4 * NTG) * 4)   // 108032 bytes

// ---------------- scratch (static device globals: allowed) ----------------
__device__ float g_Xc[(size_t)BATCH * KTOT];     // 64 MB: [x|h] concat, tf32-RN-rounded
__device__ float g_Wc[(size_t)4 * KTOT * DIMV];  // 32 MB: 4 gate weights, rounded

// ---------------- helpers ----------------
static __device__ __forceinline__ uint32_t smem_u32(const void* p) {
    uint32_t a;
    asm("{ .reg .u64 t; cvta.to.shared.u64 t, %1; cvt.u32.u64 %0, t; }" : "=r"(a) : "l"(p));
    return a;
}
static __device__ __forceinline__ void cp16(uint32_t dst, const void* src) {
    asm volatile("cp.async.cg.shared.global [%0], [%1], 16;" :: "r"(dst), "l"(src));
}
static __device__ __forceinline__ void mma_tf32(float* c, const uint32_t* a, const uint32_t* b) {
    asm volatile(
        "mma.sync.aligned.m16n8k8.row.col.f32.tf32.tf32.f32 "
        "{%0,%1,%2,%3}, {%4,%5,%6,%7}, {%8,%9}, {%0,%1,%2,%3};"
        : "+f"(c[0]), "+f"(c[1]), "+f"(c[2]), "+f"(c[3])
        : "r"(a[0]), "r"(a[1]), "r"(a[2]), "r"(a[3]), "r"(b[0]), "r"(b[1]));
}
static __device__ __forceinline__ float sigm(float v) { return 1.0f / (1.0f + __expf(-v)); }
static __device__ __forceinline__ uint32_t rtf32(float f) { return __float_as_uint(f) + 0x1000u; }

// ---------------- pre-pass: round-to-tf32 copies ----------------
__global__ void prep_x(const float* __restrict__ x, const float* __restrict__ h) {
    const size_t total = (size_t)BATCH * KTOT / 4;          // 4,194,304 float4s
    for (size_t i = (size_t)blockIdx.x * blockDim.x + threadIdx.x; i < total;
         i += (size_t)gridDim.x * blockDim.x) {
        size_t row = i >> 9;          // 512 float4 per row of 2048
        size_t c4  = i & 511;
        const float4 v = (c4 < 256)
            ? ((const float4*)(x + row * DIMV))[c4]
            : ((const float4*)(h + row * DIMV))[c4 - 256];
        uint4 u;
        u.x = rtf32(v.x); u.y = rtf32(v.y); u.z = rtf32(v.z); u.w = rtf32(v.w);
        ((uint4*)g_Xc)[i] = u;
    }
}
__global__ void prep_w(const float* __restrict__ WI, const float* __restrict__ WF,
                       const float* __restrict__ WG, const float* __restrict__ WO) {
    const size_t total = (size_t)4 * KTOT * DIMV / 4;       // 2,097,152 float4s
    for (size_t i = (size_t)blockIdx.x * blockDim.x + threadIdx.x; i < total;
         i += (size_t)gridDim.x * blockDim.x) {
        int g = (int)(i >> 19);                              // 2^19 float4 per gate
        const float* W = (g == 0) ? WI : (g == 1) ? WF : (g == 2) ? WG : WO;
        const float4 v = ((const float4*)W)[i & ((1u << 19) - 1)];
        uint4 u;
        u.x = rtf32(v.x); u.y = rtf32(v.y); u.z = rtf32(v.z); u.w = rtf32(v.w);
        ((uint4*)g_Wc)[i] = u;
    }
}

// ---------------- fused GEMM + LSTM kernel ----------------
__global__ void __launch_bounds__(NTHREADS) lstm_mma_kernel(
    const float* __restrict__ c,
    const float* __restrict__ bI, const float* __restrict__ bF,
    const float* __restrict__ bG, const float* __restrict__ bO,
    float* __restrict__ out_h, float* __restrict__ out_c)
{
    extern __shared__ __align__(16) float smem[];
    const uint32_t sbase = smem_u32(smem);
    const int tid  = threadIdx.x;
    const int lane = tid & 31;
    const int wid  = tid >> 5;
    const int nt    = blockIdx.x & (NTILES - 1);   // n fastest -> weights stay L2-resident
    const int mtile = blockIdx.x >> 5;
    const int m0 = mtile * MT;
    const int n0 = nt * NTG;

    // stage biases (128 floats) — region disjoint from pipeline stages
    if (tid < 4 * NTG) {
        int g = tid >> 5, j = tid & 31;
        const float* bsrc = (g == 0) ? bI : (g == 1) ? bF : (g == 2) ? bG : bO;
        smem[SM_BIAS_F + tid] = bsrc[n0 + j];
    }

    // ---- stage loader: A tile [128][KC], B tile [KC][4*NTG] ----
    auto loadStage = [&](int ck, int s) {
        const int k0 = ck * KC;
        const uint32_t As = sbase + (uint32_t)(s * STAGE_FLOATS) * 4;
        const uint32_t Bs = As + A_FLOATS * 4;
        const float* Xsrc = g_Xc + (size_t)m0 * KTOT + k0;
        #pragma unroll
        for (int r = 0; r < 4; r++) {                      // 1024 16B chunks of A
            int i = r * NTHREADS + tid;
            int row = i >> 3, kp = i & 7;
            cp16(As + (uint32_t)(row * APITCH + kp * 4) * 4,
                 Xsrc + (size_t)row * KTOT + kp * 4);
        }
        #pragma unroll
        for (int r = 0; r < 4; r++) {                      // 1024 16B chunks of B
            int i = r * NTHREADS + tid;
            int row = i >> 5, rem = i & 31, g = rem >> 3, p = rem & 7;
            cp16(Bs + (uint32_t)(row * BPITCH + g * NTG + p * 4) * 4,
                 g_Wc + ((size_t)g * KTOT + k0 + row) * DIMV + n0 + p * 4);
        }
        asm volatile("cp.async.commit_group;" ::: "memory");
    };

    // prologue: fill 2 stages
    loadStage(0, 0);
    loadStage(1, 1);

    const int wm = wid & 1;     // 2 warps in M (64 rows each)
    const int wn = wid >> 1;    // 4 warps in N (8 cols per gate each)

    float acc[4][4][4];         // [mtile16][gate][frag]
    #pragma unroll
    for (int mt = 0; mt < 4; mt++)
        #pragma unroll
        for (int g = 0; g < 4; g++)
            #pragma unroll
            for (int e = 0; e < 4; e++) acc[mt][g][e] = 0.0f;

    for (int ck = 0; ck < NCHUNK; ck++) {
        asm volatile("cp.async.wait_group 1;" ::: "memory");
        __syncthreads();
        if (ck + 2 < NCHUNK) loadStage(ck + 2, (ck + 2) % STAGES);
        else asm volatile("cp.async.commit_group;" ::: "memory");  // keep group accounting uniform

        const float* As = smem + (ck % STAGES) * STAGE_FLOATS;
        const float* Bs = As + A_FLOATS;

        #pragma unroll
        for (int kk = 0; kk < 4; kk++) {                   // 4 x k8 per stage
            const int kc = kk * 8 + (lane & 3);
            uint32_t a[4][4], b[4][2];
            #pragma unroll
            for (int mt = 0; mt < 4; mt++) {
                int Rm = wm * 64 + mt * 16 + (lane >> 2);
                a[mt][0] = __float_as_uint(As[Rm * APITCH + kc]);
                a[mt][1] = __float_as_uint(As[(Rm + 8) * APITCH + kc]);
                a[mt][2] = __float_as_uint(As[Rm * APITCH + kc + 4]);
                a[mt][3] = __float_as_uint(As[(Rm + 8) * APITCH + kc + 4]);
            }
            #pragma unroll
            for (int g = 0; g < 4; g++) {
                int Cn = g * NTG + wn * 8 + (lane >> 2);
                b[g][0] = __float_as_uint(Bs[kc * BPITCH + Cn]);
                b[g][1] = __float_as_uint(Bs[(kc + 4) * BPITCH + Cn]);
            }
            #pragma unroll
            for (int mt = 0; mt < 4; mt++)
                #pragma unroll
                for (int g = 0; g < 4; g++)
                    mma_tf32(acc[mt][g], a[mt], b[g]);
        }
    }
    __syncthreads();

    // ---- fused LSTM epilogue ----
    const float* bias = smem + SM_BIAS_F;
    #pragma unroll
    for (int mt = 0; mt < 4; mt++) {
        #pragma unroll
        for (int er = 0; er < 2; er++) {
            const int m = m0 + wm * 64 + mt * 16 + (lane >> 2) + er * 8;
            const int nl = wn * 8 + 2 * (lane & 3);        // even column within gate block
            const size_t off = (size_t)m * DIMV + n0 + nl;
            const float2 cv = *(const float2*)(c + off);
            float2 hh, CC;
            #pragma unroll
            for (int cc = 0; cc < 2; cc++) {
                const int e = er * 2 + cc;
                float iv = acc[mt][0][e] + bias[0 * NTG + nl + cc];
                float fv = acc[mt][1][e] + bias[1 * NTG + nl + cc];
                float gv = acc[mt][2][e] + bias[2 * NTG + nl + cc];
                float ov = acc[mt][3][e] + bias[3 * NTG + nl + cc];
                float I = sigm(iv);
                float F = sigm(fv);
                float G = tanhf(gv);
                float O = sigm(ov);
                float Cv = F * (cc ? cv.y : cv.x) + I * G;
                float Hv = O * tanhf(Cv);
                if (cc) { hh.y = Hv; CC.y = Cv; } else { hh.x = Hv; CC.x = Cv; }
            }
            *(float2*)(out_h + off) = hh;
            *(float2*)(out_c + off) = CC;
        }
    }
}

// ---------------- launch ----------------
extern "C" void kernel_launch(void* const* d_in, const int* in_sizes, int n_in,
                              void* d_out, int out_size) {
    (void)in_sizes; (void)n_in; (void)out_size;
    const float* x  = (const float*)d_in[0];
    const float* h  = (const float*)d_in[1];
    const float* c  = (const float*)d_in[2];
    const float* WI = (const float*)d_in[3];
    const float* bI = (const float*)d_in[4];
    const float* WF = (const float*)d_in[5];
    const float* bF = (const float*)d_in[6];
    const float* WG = (const float*)d_in[7];
    const float* bG = (const float*)d_in[8];
    const float* WO = (const float*)d_in[9];
    const float* bO = (const float*)d_in[10];
    float* out_h = (float*)d_out;
    float* out_c = out_h + (size_t)BATCH * DIMV;

    prep_x<<<2048, 256>>>(x, h);
    prep_w<<<2048, 256>>>(WI, WF, WG, WO);

    // idempotent, capture-safe host call — no static guards (harness rule)
    cudaFuncSetAttribute(lstm_mma_kernel,
                         cudaFuncAttributeMaxDynamicSharedMemorySize, SMEM_TOTAL);
    lstm_mma_kernel<<<MTILES * NTILES, NTHREADS, SMEM_TOTAL>>>(
        c, bI, bF, bG, bO, out_h, out_c);
}

// round 4
// speedup vs baseline: 1.1715x; 1.1715x over previous
#include <cuda_runtime.h>
#include <cstdint>

// ---------------- problem constants ----------------
#define BATCH    8192
#define DIMV     1024
#define KTOT     2048          // dimIn + dimOut
#define MT       128           // CTA M tile
#define NTG      32            // per-gate N per CTA (4 gates share same out cols)
#define NTILES   (DIMV / NTG)  // 32
#define MTILES   (BATCH / MT)  // 64
#define NTHREADS 256
#define KC       32            // K per pipeline stage
#define NCHUNK   (KTOT / KC)   // 64
#define STAGES   3

// fragment-layout tiles (no pitch waste, fully vectorizable LDS)
#define A_TILE_F   (MT * KC)               // 4096 floats = 16 KB
#define BG_TILE_F  (NTG * KC)              // 1024 floats = 4 KB per gate
#define B_TILE_F   (4 * BG_TILE_F)         // 4096 floats = 16 KB
#define STAGE_F    (A_TILE_F + B_TILE_F)   // 8192 floats = 32 KB
#define SM_BIAS_F  (STAGES * STAGE_F)      // 24576
#define SMEM_TOTAL ((SM_BIAS_F + 4 * NTG) * 4)   // 98816 bytes

// ---------------- scratch: tf32-rounded, fragment-permuted copies ----------------
// g_Xc: [mblk(64)][ck(64)][ (mb*4+kk)*32+lane ][e(4)]   (4096 floats per tile)
//   e: row = 128*mblk + 16*mb + (lane>>2) + 8*(e&1);  k = 32*ck + 8*kk + (lane&3) + 4*(e>>1)
// g_Wc: [g(4)][nblk(32)][ck(64)][ (wn*4+kk)*32+lane ][e(2)]  (1024 floats per tile)
//   e: n = 32*nblk + 8*wn + (lane>>2);  k = 32*ck + 8*kk + (lane&3) + 4*e
__device__ float g_Xc[(size_t)BATCH * KTOT];     // 64 MB
__device__ float g_Wc[(size_t)4 * KTOT * DIMV];  // 32 MB

// ---------------- helpers ----------------
static __device__ __forceinline__ uint32_t smem_u32(const void* p) {
    uint32_t a;
    asm("{ .reg .u64 t; cvta.to.shared.u64 t, %1; cvt.u32.u64 %0, t; }" : "=r"(a) : "l"(p));
    return a;
}
static __device__ __forceinline__ void cp16(uint32_t dst, const void* src) {
    asm volatile("cp.async.cg.shared.global [%0], [%1], 16;" :: "r"(dst), "l"(src));
}
static __device__ __forceinline__ void lds128(uint32_t addr, uint32_t* r) {
    asm volatile("ld.shared.v4.b32 {%0,%1,%2,%3}, [%4];"
                 : "=r"(r[0]), "=r"(r[1]), "=r"(r[2]), "=r"(r[3]) : "r"(addr));
}
static __device__ __forceinline__ void lds64(uint32_t addr, uint32_t* r) {
    asm volatile("ld.shared.v2.b32 {%0,%1}, [%2];" : "=r"(r[0]), "=r"(r[1]) : "r"(addr));
}
static __device__ __forceinline__ void mma_tf32(float* c, const uint32_t* a, const uint32_t* b) {
    asm volatile(
        "mma.sync.aligned.m16n8k8.row.col.f32.tf32.tf32.f32 "
        "{%0,%1,%2,%3}, {%4,%5,%6,%7}, {%8,%9}, {%0,%1,%2,%3};"
        : "+f"(c[0]), "+f"(c[1]), "+f"(c[2]), "+f"(c[3])
        : "r"(a[0]), "r"(a[1]), "r"(a[2]), "r"(a[3]), "r"(b[0]), "r"(b[1]));
}
static __device__ __forceinline__ float sigm(float v) { return 1.0f / (1.0f + __expf(-v)); }
static __device__ __forceinline__ uint32_t rtf32(float f) { return __float_as_uint(f) + 0x1000u; }

// ---------------- pre-pass: round + permute into fragment order ----------------
__global__ void prep_x(const float* __restrict__ x, const float* __restrict__ h) {
    const size_t total4 = (size_t)BATCH * KTOT / 4;          // 4M float4
    for (size_t o4 = (size_t)blockIdx.x * blockDim.x + threadIdx.x; o4 < total4;
         o4 += (size_t)gridDim.x * blockDim.x) {
        const int t4   = (int)(o4 & 1023);       // within-tile float4 index
        const int tile = (int)(o4 >> 10);
        const int lane = t4 & 31;
        const int kk   = (t4 >> 5) & 3;
        const int mb   = t4 >> 7;
        const int ck   = tile & 63;
        const int mblk = tile >> 6;
        const int row0 = mblk * 128 + mb * 16 + (lane >> 2);
        const int k0   = ck * 32 + kk * 8 + (lane & 3);
        const float* src = (k0 < DIMV) ? (x + k0) : (h + k0 - DIMV);
        uint4 u;
        u.x = rtf32(src[(size_t)row0 * DIMV]);
        u.y = rtf32(src[(size_t)(row0 + 8) * DIMV]);
        u.z = rtf32(src[(size_t)row0 * DIMV + 4]);
        u.w = rtf32(src[(size_t)(row0 + 8) * DIMV + 4]);
        ((uint4*)g_Xc)[o4] = u;
    }
}
__global__ void prep_w(const float* __restrict__ WI, const float* __restrict__ WF,
                       const float* __restrict__ WG, const float* __restrict__ WO) {
    const size_t total2 = (size_t)4 * KTOT * DIMV / 2;       // 4M float2
    for (size_t o2 = (size_t)blockIdx.x * blockDim.x + threadIdx.x; o2 < total2;
         o2 += (size_t)gridDim.x * blockDim.x) {
        const int t2   = (int)(o2 & 511);
        const int tile = (int)(o2 >> 9);
        const int lane = t2 & 31;
        const int kk   = (t2 >> 5) & 3;
        const int wn   = t2 >> 7;
        const int ck   = tile & 63;
        const int nblk = (tile >> 6) & 31;
        const int g    = tile >> 11;
        const float* W = (g == 0) ? WI : (g == 1) ? WF : (g == 2) ? WG : WO;
        const int n  = nblk * 32 + wn * 8 + (lane >> 2);
        const int k0 = ck * 32 + kk * 8 + (lane & 3);
        uint2 u;
        u.x = rtf32(W[(size_t)k0 * DIMV + n]);
        u.y = rtf32(W[(size_t)(k0 + 4) * DIMV + n]);
        ((uint2*)g_Wc)[o2] = u;
    }
}

// ---------------- fused GEMM + LSTM kernel ----------------
__global__ void __launch_bounds__(NTHREADS, 2) lstm_mma_kernel(
    const float* __restrict__ c,
    const float* __restrict__ bI, const float* __restrict__ bF,
    const float* __restrict__ bG, const float* __restrict__ bO,
    float* __restrict__ out_h, float* __restrict__ out_c)
{
    extern __shared__ __align__(16) float smem[];
    const uint32_t sbase = smem_u32(smem);
    const int tid  = threadIdx.x;
    const int lane = tid & 31;
    const int wid  = tid >> 5;
    const int nt    = blockIdx.x & (NTILES - 1);   // n fastest -> weights stay L2-resident
    const int mtile = blockIdx.x >> 5;
    const int m0 = mtile * MT;
    const int n0 = nt * NTG;

    // stage biases (128 floats)
    if (tid < 4 * NTG) {
        int g = tid >> 5, j = tid & 31;
        const float* bsrc = (g == 0) ? bI : (g == 1) ? bF : (g == 2) ? bG : bO;
        smem[SM_BIAS_F + tid] = bsrc[n0 + j];
    }

    // ---- stage loader: contiguous fragment-layout tiles ----
    auto loadStage = [&](int ck, int s) {
        const uint32_t As = sbase + (uint32_t)(s * STAGE_F) * 4;
        const uint32_t Bs = As + A_TILE_F * 4;
        const float* Asrc = g_Xc + ((size_t)mtile * 64 + ck) * A_TILE_F;
        #pragma unroll
        for (int r = 0; r < 4; r++) {            // 1024 16B chunks of A
            int i = r * NTHREADS + tid;
            cp16(As + (uint32_t)i * 16, Asrc + (size_t)i * 4);
        }
        #pragma unroll
        for (int r = 0; r < 4; r++) {            // 1024 16B chunks of B (4 gates x 256)
            int i = r * NTHREADS + tid;
            int g = i >> 8, w = i & 255;
            cp16(Bs + (uint32_t)i * 16,
                 g_Wc + (((size_t)g * 32 + nt) * 64 + ck) * BG_TILE_F + (size_t)w * 4);
        }
        asm volatile("cp.async.commit_group;" ::: "memory");
    };

    loadStage(0, 0);
    loadStage(1, 1);

    const int wm = wid & 1;     // 2 warps in M (64 rows each)
    const int wn = wid >> 1;    // 4 warps in N (8 cols per gate each)

    float acc[4][4][4];
    #pragma unroll
    for (int mt = 0; mt < 4; mt++)
        #pragma unroll
        for (int g = 0; g < 4; g++)
            #pragma unroll
            for (int e = 0; e < 4; e++) acc[mt][g][e] = 0.0f;

    // per-thread fragment base offsets (bytes within stage)
    const uint32_t a_base = (uint32_t)(wm * 4 * 2048 + lane * 16);          // + mt*2048 + kk*512
    const uint32_t b_base = (uint32_t)(A_TILE_F * 4 + wn * 1024 + lane * 8); // + g*4096 + kk*256

    for (int ck = 0; ck < NCHUNK; ck++) {
        asm volatile("cp.async.wait_group 1;" ::: "memory");
        __syncthreads();
        if (ck + 2 < NCHUNK) loadStage(ck + 2, (ck + 2) % STAGES);
        else asm volatile("cp.async.commit_group;" ::: "memory");

        const uint32_t stg = sbase + (uint32_t)((ck % STAGES) * STAGE_F) * 4;
        #pragma unroll
        for (int kk = 0; kk < 4; kk++) {
            uint32_t a[4][4], b[4][2];
            #pragma unroll
            for (int mt = 0; mt < 4; mt++)
                lds128(stg + a_base + mt * 2048 + kk * 512, a[mt]);
            #pragma unroll
            for (int g = 0; g < 4; g++)
                lds64(stg + b_base + g * 4096 + kk * 256, b[g]);
            #pragma unroll
            for (int mt = 0; mt < 4; mt++)
                #pragma unroll
                for (int g = 0; g < 4; g++)
                    mma_tf32(acc[mt][g], a[mt], b[g]);
        }
    }
    __syncthreads();

    // ---- fused LSTM epilogue ----
    const float* bias = smem + SM_BIAS_F;
    #pragma unroll
    for (int mt = 0; mt < 4; mt++) {
        #pragma unroll
        for (int er = 0; er < 2; er++) {
            const int m = m0 + wm * 64 + mt * 16 + (lane >> 2) + er * 8;
            const int nl = wn * 8 + 2 * (lane & 3);
            const size_t off = (size_t)m * DIMV + n0 + nl;
            const float2 cv = *(const float2*)(c + off);
            float2 hh, CC;
            #pragma unroll
            for (int cc = 0; cc < 2; cc++) {
                const int e = er * 2 + cc;
                float iv = acc[mt][0][e] + bias[0 * NTG + nl + cc];
                float fv = acc[mt][1][e] + bias[1 * NTG + nl + cc];
                float gv = acc[mt][2][e] + bias[2 * NTG + nl + cc];
                float ov = acc[mt][3][e] + bias[3 * NTG + nl + cc];
                float I = sigm(iv);
                float F = sigm(fv);
                float G = tanhf(gv);
                float O = sigm(ov);
                float Cv = F * (cc ? cv.y : cv.x) + I * G;
                float Hv = O * tanhf(Cv);
                if (cc) { hh.y = Hv; CC.y = Cv; } else { hh.x = Hv; CC.x = Cv; }
            }
            *(float2*)(out_h + off) = hh;
            *(float2*)(out_c + off) = CC;
        }
    }
}

// ---------------- launch ----------------
extern "C" void kernel_launch(void* const* d_in, const int* in_sizes, int n_in,
                              void* d_out, int out_size) {
    (void)in_sizes; (void)n_in; (void)out_size;
    const float* x  = (const float*)d_in[0];
    const float* h  = (const float*)d_in[1];
    const float* c  = (const float*)d_in[2];
    const float* WI = (const float*)d_in[3];
    const float* bI = (const float*)d_in[4];
    const float* WF = (const float*)d_in[5];
    const float* bF = (const float*)d_in[6];
    const float* WG = (const float*)d_in[7];
    const float* bG = (const float*)d_in[8];
    const float* WO = (const float*)d_in[9];
    const float* bO = (const float*)d_in[10];
    float* out_h = (float*)d_out;
    float* out_c = out_h + (size_t)BATCH * DIMV;

    prep_x<<<2048, 256>>>(x, h);
    prep_w<<<2048, 256>>>(WI, WF, WG, WO);

    cudaFuncSetAttribute(lstm_mma_kernel,
                         cudaFuncAttributeMaxDynamicSharedMemorySize, SMEM_TOTAL);
    lstm_mma_kernel<<<MTILES * NTILES, NTHREADS, SMEM_TOTAL>>>(
        c, bI, bF, bG, bO, out_h, out_c);
}

// round 7
// speedup vs baseline: 2.0793x; 1.7749x over previous
#include <cuda_runtime.h>
#include <cuda_fp16.h>
#include <cstdint>

// ---------------- problem constants ----------------
#define BATCH    8192
#define DIMV     1024
#define KTOT     2048          // dimIn + dimOut
#define MT       128           // CTA M tile
#define NTG      32            // per-gate N per CTA
#define NTILES   (DIMV / NTG)  // 32
#define MTILES   (BATCH / MT)  // 64
#define NTHREADS 256
#define KC       32            // K per pipeline stage
#define NCHUNK   (KTOT / KC)   // 64
#define STAGES   3

// fp16 fragment-layout tiles
#define A_TILE_B   (MT * KC * 2)           // 8192 bytes
#define BG_TILE_B  (NTG * KC * 2)          // 2048 bytes per gate
#define B_TILE_B   (4 * BG_TILE_B)         // 8192 bytes
#define STAGE_B    (A_TILE_B + B_TILE_B)   // 16384 bytes
#define SM_BIAS_B  (STAGES * STAGE_B)      // 49152
#define SMEM_TOTAL (SM_BIAS_B + 4 * NTG * 4)   // 49664 bytes

// ---------------- scratch: fp16, fragment-permuted copies ----------------
// g_Xh: [mblk(64)][ck(64)][mb(8)][k16(2)][lane(32)][4xb32]  (8192 B per (mblk,ck) tile)
// g_Wh: [g(4)][nblk(32)][ck(64)][n8(4)][k16(2)][lane(32)][2xb32]  (2048 B per tile)
__device__ __half g_Xh[(size_t)BATCH * KTOT];     // 32 MB = 2^21 16B units
__device__ __half g_Wh[(size_t)4 * KTOT * DIMV];  // 16 MB = 2^21 8B units

// ---------------- helpers ----------------
static __device__ __forceinline__ uint32_t smem_u32(const void* p) {
    uint32_t a;
    asm("{ .reg .u64 t; cvta.to.shared.u64 t, %1; cvt.u32.u64 %0, t; }" : "=r"(a) : "l"(p));
    return a;
}
static __device__ __forceinline__ void cp16(uint32_t dst, const void* src) {
    asm volatile("cp.async.cg.shared.global [%0], [%1], 16;" :: "r"(dst), "l"(src));
}
static __device__ __forceinline__ void lds128(uint32_t addr, uint32_t* r) {
    asm volatile("ld.shared.v4.b32 {%0,%1,%2,%3}, [%4];"
                 : "=r"(r[0]), "=r"(r[1]), "=r"(r[2]), "=r"(r[3]) : "r"(addr));
}
static __device__ __forceinline__ void lds64(uint32_t addr, uint32_t* r) {
    asm volatile("ld.shared.v2.b32 {%0,%1}, [%2];" : "=r"(r[0]), "=r"(r[1]) : "r"(addr));
}
static __device__ __forceinline__ void mma_f16(float* c, const uint32_t* a, const uint32_t* b) {
    asm volatile(
        "mma.sync.aligned.m16n8k16.row.col.f32.f16.f16.f32 "
        "{%0,%1,%2,%3}, {%4,%5,%6,%7}, {%8,%9}, {%0,%1,%2,%3};"
        : "+f"(c[0]), "+f"(c[1]), "+f"(c[2]), "+f"(c[3])
        : "r"(a[0]), "r"(a[1]), "r"(a[2]), "r"(a[3]), "r"(b[0]), "r"(b[1]));
}
static __device__ __forceinline__ float sigm(float v) { return 1.0f / (1.0f + __expf(-v)); }
static __device__ __forceinline__ uint32_t packh2(float lo, float hi) {
    __half2 t = __floats2half2_rn(lo, hi);
    return *reinterpret_cast<uint32_t*>(&t);
}

// ---------------- pre-pass: round to fp16 + permute into m16n8k16 fragment order ----
__global__ void prep_x(const float* __restrict__ x, const float* __restrict__ h) {
    const size_t total = (size_t)1 << 21;                    // 2M 16B units (32 MB)
    for (size_t u = (size_t)blockIdx.x * blockDim.x + threadIdx.x; u < total;
         u += (size_t)gridDim.x * blockDim.x) {
        const int lane = (int)(u & 31);
        const int k16  = (int)((u >> 5) & 1);
        const int mb   = (int)((u >> 6) & 7);
        const int ck   = (int)((u >> 9) & 63);
        const int mblk = (int)(u >> 15);                     // 0..63
        const int row  = mblk * 128 + mb * 16 + (lane >> 2);
        const int k    = ck * 32 + k16 * 16 + (lane & 3) * 2;
        const float* src = (k < DIMV) ? (x + k) : (h + k - DIMV);
        const size_t r0 = (size_t)row * DIMV, r8 = (size_t)(row + 8) * DIMV;
        uint4 o;
        o.x = packh2(src[r0],     src[r0 + 1]);
        o.y = packh2(src[r8],     src[r8 + 1]);
        o.z = packh2(src[r0 + 8], src[r0 + 9]);
        o.w = packh2(src[r8 + 8], src[r8 + 9]);
        ((uint4*)g_Xh)[u] = o;
    }
}
__global__ void prep_w(const float* __restrict__ WI, const float* __restrict__ WF,
                       const float* __restrict__ WG, const float* __restrict__ WO) {
    const size_t total = (size_t)1 << 21;                    // 2M 8B units (16 MB)
    for (size_t u = (size_t)blockIdx.x * blockDim.x + threadIdx.x; u < total;
         u += (size_t)gridDim.x * blockDim.x) {
        const int lane = (int)(u & 31);
        const int k16  = (int)((u >> 5) & 1);
        const int n8   = (int)((u >> 6) & 3);
        const int ck   = (int)((u >> 8) & 63);
        const int nblk = (int)((u >> 14) & 31);
        const int g    = (int)(u >> 19);                     // 0..3
        const float* W = (g == 0) ? WI : (g == 1) ? WF : (g == 2) ? WG : WO;
        const int n = nblk * 32 + n8 * 8 + (lane >> 2);
        const int k = ck * 32 + k16 * 16 + (lane & 3) * 2;
        uint2 o;
        o.x = packh2(W[(size_t)k * DIMV + n],       W[(size_t)(k + 1) * DIMV + n]);
        o.y = packh2(W[(size_t)(k + 8) * DIMV + n], W[(size_t)(k + 9) * DIMV + n]);
        ((uint2*)g_Wh)[u] = o;
    }
}

// ---------------- fused GEMM + LSTM kernel ----------------
__global__ void __launch_bounds__(NTHREADS, 2) lstm_mma_kernel(
    const float* __restrict__ c,
    const float* __restrict__ bI, const float* __restrict__ bF,
    const float* __restrict__ bG, const float* __restrict__ bO,
    float* __restrict__ out_h, float* __restrict__ out_c)
{
    extern __shared__ __align__(16) char smem[];
    const uint32_t sbase = smem_u32(smem);
    const int tid  = threadIdx.x;
    const int lane = tid & 31;
    const int wid  = tid >> 5;
    const int nt    = blockIdx.x & (NTILES - 1);   // n fastest -> weights stay L2-resident
    const int mtile = blockIdx.x >> 5;
    const int m0 = mtile * MT;
    const int n0 = nt * NTG;

    // stage biases (128 floats) past the pipeline stages
    if (tid < 4 * NTG) {
        int g = tid >> 5, j = tid & 31;
        const float* bsrc = (g == 0) ? bI : (g == 1) ? bF : (g == 2) ? bG : bO;
        ((float*)(smem + SM_BIAS_B))[tid] = bsrc[n0 + j];
    }

    // ---- stage loader: 1024 16B chunks (512 A + 512 B) ----
    auto loadStage = [&](int ck, int s) {
        const uint32_t As = sbase + (uint32_t)(s * STAGE_B);
        const uint32_t Bs = As + A_TILE_B;
        const char* Asrc = (const char*)g_Xh + ((size_t)mtile * 64 + ck) * A_TILE_B;
        #pragma unroll
        for (int r = 0; r < 2; r++) {            // 512 chunks of A
            int i = r * NTHREADS + tid;
            cp16(As + (uint32_t)i * 16, Asrc + (size_t)i * 16);
        }
        #pragma unroll
        for (int r = 0; r < 2; r++) {            // 512 chunks of B (4 gates x 128)
            int i = r * NTHREADS + tid;
            int g = i >> 7, w = i & 127;
            cp16(Bs + (uint32_t)i * 16,
                 (const char*)g_Wh + (((size_t)g * 32 + nt) * 64 + ck) * BG_TILE_B
                                   + (size_t)w * 16);
        }
        asm volatile("cp.async.commit_group;" ::: "memory");
    };

    loadStage(0, 0);
    loadStage(1, 1);

    const int wm = wid & 1;     // 2 warps in M (64 rows each)
    const int wn = wid >> 1;    // 4 warps in N (8 cols per gate each)

    float acc[4][4][4];
    #pragma unroll
    for (int mt = 0; mt < 4; mt++)
        #pragma unroll
        for (int g = 0; g < 4; g++)
            #pragma unroll
            for (int e = 0; e < 4; e++) acc[mt][g][e] = 0.0f;

    // byte offsets within a stage
    // A: [mb(8)][k16(2)][lane][16B] ; this warp's mb = wm*4 + mt
    const uint32_t a_base = (uint32_t)(wm * 4 * 1024 + lane * 16);   // + mt*1024 + k16*512
    // B: [g][n8(4)][k16(2)][lane][8B] ; this warp's n8 = wn
    const uint32_t b_base = (uint32_t)(A_TILE_B + wn * 512 + lane * 8); // + g*2048 + k16*256

    for (int ck = 0; ck < NCHUNK; ck++) {
        asm volatile("cp.async.wait_group 1;" ::: "memory");
        __syncthreads();
        if (ck + 2 < NCHUNK) loadStage(ck + 2, (ck + 2) % STAGES);
        else asm volatile("cp.async.commit_group;" ::: "memory");

        const uint32_t stg = sbase + (uint32_t)((ck % STAGES) * STAGE_B);
        #pragma unroll
        for (int k16 = 0; k16 < 2; k16++) {
            uint32_t a[4][4], b[4][2];
            #pragma unroll
            for (int mt = 0; mt < 4; mt++)
                lds128(stg + a_base + mt * 1024 + k16 * 512, a[mt]);
            #pragma unroll
            for (int g = 0; g < 4; g++)
                lds64(stg + b_base + g * 2048 + k16 * 256, b[g]);
            #pragma unroll
            for (int mt = 0; mt < 4; mt++)
                #pragma unroll
                for (int g = 0; g < 4; g++)
                    mma_f16(acc[mt][g], a[mt], b[g]);
        }
    }
    __syncthreads();

    // ---- fused LSTM epilogue ----
    const float* bias = (const float*)(smem + SM_BIAS_B);
    #pragma unroll
    for (int mt = 0; mt < 4; mt++) {
        #pragma unroll
        for (int er = 0; er < 2; er++) {
            const int m = m0 + wm * 64 + mt * 16 + (lane >> 2) + er * 8;
            const int nl = wn * 8 + 2 * (lane & 3);
            const size_t off = (size_t)m * DIMV + n0 + nl;
            const float2 cv = *(const float2*)(c + off);
            float2 hh, CC;
            #pragma unroll
            for (int cc = 0; cc < 2; cc++) {
                const int e = er * 2 + cc;
                float iv = acc[mt][0][e] + bias[0 * NTG + nl + cc];
                float fv = acc[mt][1][e] + bias[1 * NTG + nl + cc];
                float gv = acc[mt][2][e] + bias[2 * NTG + nl + cc];
                float ov = acc[mt][3][e] + bias[3 * NTG + nl + cc];
                float I = sigm(iv);
                float F = sigm(fv);
                float G = tanhf(gv);
                float O = sigm(ov);
                float Cv = F * (cc ? cv.y : cv.x) + I * G;
                float Hv = O * tanhf(Cv);
                if (cc) { hh.y = Hv; CC.y = Cv; } else { hh.x = Hv; CC.x = Cv; }
            }
            *(float2*)(out_h + off) = hh;
            *(float2*)(out_c + off) = CC;
        }
    }
}

// ---------------- launch ----------------
extern "C" void kernel_launch(void* const* d_in, const int* in_sizes, int n_in,
                              void* d_out, int out_size) {
    (void)in_sizes; (void)n_in; (void)out_size;
    const float* x  = (const float*)d_in[0];
    const float* h  = (const float*)d_in[1];
    const float* c  = (const float*)d_in[2];
    const float* WI = (const float*)d_in[3];
    const float* bI = (const float*)d_in[4];
    const float* WF = (const float*)d_in[5];
    const float* bF = (const float*)d_in[6];
    const float* WG = (const float*)d_in[7];
    const float* bG = (const float*)d_in[8];
    const float* WO = (const float*)d_in[9];
    const float* bO = (const float*)d_in[10];
    float* out_h = (float*)d_out;
    float* out_c = out_h + (size_t)BATCH * DIMV;

    prep_x<<<2048, 256>>>(x, h);
    prep_w<<<2048, 256>>>(WI, WF, WG, WO);

    cudaFuncSetAttribute(lstm_mma_kernel,
                         cudaFuncAttributeMaxDynamicSharedMemorySize, SMEM_TOTAL);
    lstm_mma_kernel<<<MTILES * NTILES, NTHREADS, SMEM_TOTAL>>>(
        c, bI, bF, bG, bO, out_h, out_c);
}

// round 8
// speedup vs baseline: 2.1542x; 1.0361x over previous
#include <cuda_runtime.h>
#include <cuda_fp16.h>
#include <cstdint>

// ---------------- problem constants ----------------
#define BATCH    8192
#define DIMV     1024
#define KTOT     2048          // dimIn + dimOut
#define MT       128           // CTA M tile
#define NTG      32            // per-gate N per CTA
#define NTILES   (DIMV / NTG)  // 32
#define MTILES   (BATCH / MT)  // 64
#define NTHREADS 256
#define KC       64            // K per pipeline stage (2 scratch ck-tiles)
#define NCHUNK   (KTOT / KC)   // 32
#define STAGES   3

// fp16 fragment-layout tiles (per 64-K stage)
#define A_TILE_B   (MT * KC * 2)           // 16384 bytes
#define BG_TILE_B  (NTG * KC * 2)          // 4096 bytes per gate
#define B_TILE_B   (4 * BG_TILE_B)         // 16384 bytes
#define STAGE_B    (A_TILE_B + B_TILE_B)   // 32768 bytes
#define SM_BIAS_B  (STAGES * STAGE_B)      // 98304
#define SMEM_TOTAL (SM_BIAS_B + 4 * NTG * 4)   // 98816 bytes

// ---------------- scratch: fp16, fragment-permuted copies ----------------
// g_Xh: [mblk(64)][ck32(64)][mb(8)][k16(2)][lane(32)][4xb32]  (8192 B per ck32 tile)
// g_Wh: [g(4)][nblk(32)][ck32(64)][n8(4)][k16(2)][lane(32)][2xb32]  (2048 B per tile)
__device__ __half g_Xh[(size_t)BATCH * KTOT];     // 32 MB = 2^21 16B units
__device__ __half g_Wh[(size_t)4 * KTOT * DIMV];  // 16 MB = 2^21 8B units

// ---------------- helpers ----------------
static __device__ __forceinline__ uint32_t smem_u32(const void* p) {
    uint32_t a;
    asm("{ .reg .u64 t; cvta.to.shared.u64 t, %1; cvt.u32.u64 %0, t; }" : "=r"(a) : "l"(p));
    return a;
}
static __device__ __forceinline__ void cp16(uint32_t dst, const void* src) {
    asm volatile("cp.async.cg.shared.global [%0], [%1], 16;" :: "r"(dst), "l"(src));
}
static __device__ __forceinline__ void lds128(uint32_t addr, uint32_t* r) {
    asm volatile("ld.shared.v4.b32 {%0,%1,%2,%3}, [%4];"
                 : "=r"(r[0]), "=r"(r[1]), "=r"(r[2]), "=r"(r[3]) : "r"(addr));
}
static __device__ __forceinline__ void lds64(uint32_t addr, uint32_t* r) {
    asm volatile("ld.shared.v2.b32 {%0,%1}, [%2];" : "=r"(r[0]), "=r"(r[1]) : "r"(addr));
}
static __device__ __forceinline__ void mma_f16(float* c, const uint32_t* a, const uint32_t* b) {
    asm volatile(
        "mma.sync.aligned.m16n8k16.row.col.f32.f16.f16.f32 "
        "{%0,%1,%2,%3}, {%4,%5,%6,%7}, {%8,%9}, {%0,%1,%2,%3};"
        : "+f"(c[0]), "+f"(c[1]), "+f"(c[2]), "+f"(c[3])
        : "r"(a[0]), "r"(a[1]), "r"(a[2]), "r"(a[3]), "r"(b[0]), "r"(b[1]));
}
static __device__ __forceinline__ float sigm(float v) { return 1.0f / (1.0f + __expf(-v)); }
static __device__ __forceinline__ uint32_t packh2(float lo, float hi) {
    __half2 t = __floats2half2_rn(lo, hi);
    return *reinterpret_cast<uint32_t*>(&t);
}

// ---------------- pre-pass (single launch): round to fp16 + permute ----------------
__global__ void prep_all(const float* __restrict__ x, const float* __restrict__ h,
                         const float* __restrict__ WI, const float* __restrict__ WF,
                         const float* __restrict__ WG, const float* __restrict__ WO) {
    const size_t totalX = (size_t)1 << 21;                   // 2M 16B units (32 MB)
    const size_t totalW = (size_t)1 << 21;                   // 2M 8B units (16 MB)
    for (size_t t = (size_t)blockIdx.x * blockDim.x + threadIdx.x; t < totalX + totalW;
         t += (size_t)gridDim.x * blockDim.x) {
        if (t < totalX) {
            const size_t u = t;
            const int lane = (int)(u & 31);
            const int k16  = (int)((u >> 5) & 1);
            const int mb   = (int)((u >> 6) & 7);
            const int ck   = (int)((u >> 9) & 63);
            const int mblk = (int)(u >> 15);                 // 0..63
            const int row  = mblk * 128 + mb * 16 + (lane >> 2);
            const int k    = ck * 32 + k16 * 16 + (lane & 3) * 2;
            const float* src = (k < DIMV) ? (x + k) : (h + k - DIMV);
            const size_t r0 = (size_t)row * DIMV, r8 = (size_t)(row + 8) * DIMV;
            uint4 o;
            o.x = packh2(src[r0],     src[r0 + 1]);
            o.y = packh2(src[r8],     src[r8 + 1]);
            o.z = packh2(src[r0 + 8], src[r0 + 9]);
            o.w = packh2(src[r8 + 8], src[r8 + 9]);
            ((uint4*)g_Xh)[u] = o;
        } else {
            const size_t u = t - totalX;
            const int lane = (int)(u & 31);
            const int k16  = (int)((u >> 5) & 1);
            const int n8   = (int)((u >> 6) & 3);
            const int ck   = (int)((u >> 8) & 63);
            const int nblk = (int)((u >> 14) & 31);
            const int g    = (int)(u >> 19);                 // 0..3
            const float* W = (g == 0) ? WI : (g == 1) ? WF : (g == 2) ? WG : WO;
            const int n = nblk * 32 + n8 * 8 + (lane >> 2);
            const int k = ck * 32 + k16 * 16 + (lane & 3) * 2;
            uint2 o;
            o.x = packh2(W[(size_t)k * DIMV + n],       W[(size_t)(k + 1) * DIMV + n]);
            o.y = packh2(W[(size_t)(k + 8) * DIMV + n], W[(size_t)(k + 9) * DIMV + n]);
            ((uint2*)g_Wh)[u] = o;
        }
    }
}

// ---------------- fused GEMM + LSTM kernel ----------------
__global__ void __launch_bounds__(NTHREADS, 2) lstm_mma_kernel(
    const float* __restrict__ c,
    const float* __restrict__ bI, const float* __restrict__ bF,
    const float* __restrict__ bG, const float* __restrict__ bO,
    float* __restrict__ out_h, float* __restrict__ out_c)
{
    extern __shared__ __align__(16) char smem[];
    const uint32_t sbase = smem_u32(smem);
    const int tid  = threadIdx.x;
    const int lane = tid & 31;
    const int wid  = tid >> 5;
    const int nt    = blockIdx.x & (NTILES - 1);   // n fastest -> weights stay L2-resident
    const int mtile = blockIdx.x >> 5;
    const int m0 = mtile * MT;
    const int n0 = nt * NTG;

    // stage biases (128 floats) past the pipeline stages
    if (tid < 4 * NTG) {
        int g = tid >> 5, j = tid & 31;
        const float* bsrc = (g == 0) ? bI : (g == 1) ? bF : (g == 2) ? bG : bO;
        ((float*)(smem + SM_BIAS_B))[tid] = bsrc[n0 + j];
    }

    // ---- stage loader: 2048 16B chunks (1024 A + 1024 B); 8 cp16/thread ----
    auto loadStage = [&](int ckp, int s) {
        const uint32_t As = sbase + (uint32_t)(s * STAGE_B);
        const uint32_t Bs = As + A_TILE_B;
        // A: two adjacent 8KB ck32-tiles = 16KB contiguous
        const char* Asrc = (const char*)g_Xh + ((size_t)mtile * 64 + (size_t)ckp * 2) * 8192;
        #pragma unroll
        for (int r = 0; r < 4; r++) {
            int i = r * NTHREADS + tid;
            cp16(As + (uint32_t)i * 16, Asrc + (size_t)i * 16);
        }
        // B: per gate, two adjacent 2KB tiles = 4KB contiguous
        #pragma unroll
        for (int r = 0; r < 4; r++) {
            int i = r * NTHREADS + tid;
            int g = i >> 8, w = i & 255;
            cp16(Bs + (uint32_t)i * 16,
                 (const char*)g_Wh + (((size_t)g * 32 + nt) * 64 + (size_t)ckp * 2) * 2048
                                   + (size_t)w * 16);
        }
        asm volatile("cp.async.commit_group;" ::: "memory");
    };

    loadStage(0, 0);
    loadStage(1, 1);

    const int wm = wid & 1;     // 2 warps in M (64 rows each)
    const int wn = wid >> 1;    // 4 warps in N (8 cols per gate each)

    float acc[4][4][4];
    #pragma unroll
    for (int mt = 0; mt < 4; mt++)
        #pragma unroll
        for (int g = 0; g < 4; g++)
            #pragma unroll
            for (int e = 0; e < 4; e++) acc[mt][g][e] = 0.0f;

    // byte offsets within a stage (ks = k16 index 0..3)
    // A: (ks>>1)*8192 + (wm*4+mt)*1024 + (ks&1)*512 + lane*16
    const uint32_t a_base = (uint32_t)(wm * 4 * 1024 + lane * 16);
    // B: A_TILE_B + g*4096 + (ks>>1)*2048 + wn*512 + (ks&1)*256 + lane*8
    const uint32_t b_base = (uint32_t)(A_TILE_B + wn * 512 + lane * 8);

    for (int ck = 0; ck < NCHUNK; ck++) {
        asm volatile("cp.async.wait_group 1;" ::: "memory");
        __syncthreads();
        if (ck + 2 < NCHUNK) loadStage(ck + 2, (ck + 2) % STAGES);
        else asm volatile("cp.async.commit_group;" ::: "memory");

        const uint32_t stg = sbase + (uint32_t)((ck % STAGES) * STAGE_B);
        #pragma unroll
        for (int ks = 0; ks < 4; ks++) {
            const uint32_t ka = (uint32_t)((ks >> 1) * 8192 + (ks & 1) * 512);
            const uint32_t kb = (uint32_t)((ks >> 1) * 2048 + (ks & 1) * 256);
            uint32_t a[4][4], b[4][2];
            #pragma unroll
            for (int mt = 0; mt < 4; mt++)
                lds128(stg + a_base + ka + mt * 1024, a[mt]);
            #pragma unroll
            for (int g = 0; g < 4; g++)
                lds64(stg + b_base + kb + g * 4096, b[g]);
            #pragma unroll
            for (int mt = 0; mt < 4; mt++)
                #pragma unroll
                for (int g = 0; g < 4; g++)
                    mma_f16(acc[mt][g], a[mt], b[g]);
        }
    }
    __syncthreads();

    // ---- fused LSTM epilogue ----
    const float* bias = (const float*)(smem + SM_BIAS_B);
    #pragma unroll
    for (int mt = 0; mt < 4; mt++) {
        #pragma unroll
        for (int er = 0; er < 2; er++) {
            const int m = m0 + wm * 64 + mt * 16 + (lane >> 2) + er * 8;
            const int nl = wn * 8 + 2 * (lane & 3);
            const size_t off = (size_t)m * DIMV + n0 + nl;
            const float2 cv = *(const float2*)(c + off);
            float2 hh, CC;
            #pragma unroll
            for (int cc = 0; cc < 2; cc++) {
                const int e = er * 2 + cc;
                float iv = acc[mt][0][e] + bias[0 * NTG + nl + cc];
                float fv = acc[mt][1][e] + bias[1 * NTG + nl + cc];
                float gv = acc[mt][2][e] + bias[2 * NTG + nl + cc];
                float ov = acc[mt][3][e] + bias[3 * NTG + nl + cc];
                float I = sigm(iv);
                float F = sigm(fv);
                float G = tanhf(gv);
                float O = sigm(ov);
                float Cv = F * (cc ? cv.y : cv.x) + I * G;
                float Hv = O * tanhf(Cv);
                if (cc) { hh.y = Hv; CC.y = Cv; } else { hh.x = Hv; CC.x = Cv; }
            }
            *(float2*)(out_h + off) = hh;
            *(float2*)(out_c + off) = CC;
        }
    }
}

// ---------------- launch ----------------
extern "C" void kernel_launch(void* const* d_in, const int* in_sizes, int n_in,
                              void* d_out, int out_size) {
    (void)in_sizes; (void)n_in; (void)out_size;
    const float* x  = (const float*)d_in[0];
    const float* h  = (const float*)d_in[1];
    const float* c  = (const float*)d_in[2];
    const float* WI = (const float*)d_in[3];
    const float* bI = (const float*)d_in[4];
    const float* WF = (const float*)d_in[5];
    const float* bF = (const float*)d_in[6];
    const float* WG = (const float*)d_in[7];
    const float* bG = (const float*)d_in[8];
    const float* WO = (const float*)d_in[9];
    const float* bO = (const float*)d_in[10];
    float* out_h = (float*)d_out;
    float* out_c = out_h + (size_t)BATCH * DIMV;

    prep_all<<<3072, 256>>>(x, h, WI, WF, WG, WO);

    cudaFuncSetAttribute(lstm_mma_kernel,
                         cudaFuncAttributeMaxDynamicSharedMemorySize, SMEM_TOTAL);
    lstm_mma_kernel<<<MTILES * NTILES, NTHREADS, SMEM_TOTAL>>>(
        c, bI, bF, bG, bO, out_h, out_c);
}

// round 9
// speedup vs baseline: 2.1589x; 1.0021x over previous
#include <cuda_runtime.h>
#include <cuda_fp16.h>
#include <cstdint>

// ---------------- problem constants ----------------
#define BATCH    8192
#define DIMV     1024
#define KTOT     2048          // dimIn + dimOut
#define MT       128           // CTA M tile
#define NTG      32            // per-gate N per CTA
#define NTILES   (DIMV / NTG)  // 32
#define MTILES   (BATCH / MT)  // 64
#define NTHREADS 256
#define KC       64            // K per pipeline stage (2 scratch ck-tiles)
#define NCHUNK   (KTOT / KC)   // 32
#define STAGES   3

// fp16 fragment-layout tiles (per 64-K stage)
#define A_TILE_B   (MT * KC * 2)           // 16384 bytes
#define BG_TILE_B  (NTG * KC * 2)          // 4096 bytes per gate
#define B_TILE_B   (4 * BG_TILE_B)         // 16384 bytes
#define STAGE_B    (A_TILE_B + B_TILE_B)   // 32768 bytes
#define SM_BIAS_B  (STAGES * STAGE_B)      // 98304
#define SMEM_TOTAL (SM_BIAS_B + 4 * NTG * 4)   // 98816 bytes

// ---------------- scratch: fp16, fragment-permuted copies ----------------
// g_Xh: [mblk(64)][ck32(64)][mb(8)][k16(2)][lane(32)][4xb32]  (8192 B per ck32 tile)
// g_Wh: [g(4)][nblk(32)][ck32(64)][n8(4)][k16(2)][lane(32)][2xb32]  (2048 B per tile)
__device__ __half g_Xh[(size_t)BATCH * KTOT];     // 32 MB = 2^21 16B units
__device__ __half g_Wh[(size_t)4 * KTOT * DIMV];  // 16 MB = 2^21 8B units

// ---------------- helpers ----------------
static __device__ __forceinline__ uint32_t smem_u32(const void* p) {
    uint32_t a;
    asm("{ .reg .u64 t; cvta.to.shared.u64 t, %1; cvt.u32.u64 %0, t; }" : "=r"(a) : "l"(p));
    return a;
}
static __device__ __forceinline__ void cp16(uint32_t dst, const void* src) {
    asm volatile("cp.async.cg.shared.global [%0], [%1], 16;" :: "r"(dst), "l"(src));
}
static __device__ __forceinline__ void lds128(uint32_t addr, uint32_t* r) {
    asm volatile("ld.shared.v4.b32 {%0,%1,%2,%3}, [%4];"
                 : "=r"(r[0]), "=r"(r[1]), "=r"(r[2]), "=r"(r[3]) : "r"(addr));
}
static __device__ __forceinline__ void lds64(uint32_t addr, uint32_t* r) {
    asm volatile("ld.shared.v2.b32 {%0,%1}, [%2];" : "=r"(r[0]), "=r"(r[1]) : "r"(addr));
}
static __device__ __forceinline__ void mma_f16(float* c, const uint32_t* a, const uint32_t* b) {
    asm volatile(
        "mma.sync.aligned.m16n8k16.row.col.f32.f16.f16.f32 "
        "{%0,%1,%2,%3}, {%4,%5,%6,%7}, {%8,%9}, {%0,%1,%2,%3};"
        : "+f"(c[0]), "+f"(c[1]), "+f"(c[2]), "+f"(c[3])
        : "r"(a[0]), "r"(a[1]), "r"(a[2]), "r"(a[3]), "r"(b[0]), "r"(b[1]));
}
static __device__ __forceinline__ float sigm(float v) { return 1.0f / (1.0f + __expf(-v)); }
static __device__ __forceinline__ uint32_t packh2(float lo, float hi) {
    __half2 t = __floats2half2_rn(lo, hi);
    return *reinterpret_cast<uint32_t*>(&t);
}

// ---------------- pre-pass (single launch): round to fp16 + permute ----------------
__global__ void prep_all(const float* __restrict__ x, const float* __restrict__ h,
                         const float* __restrict__ WI, const float* __restrict__ WF,
                         const float* __restrict__ WG, const float* __restrict__ WO) {
    const size_t totalX = (size_t)1 << 21;                   // 2M 16B units (32 MB)
    const size_t totalW = (size_t)1 << 21;                   // 2M 8B units (16 MB)
    for (size_t t = (size_t)blockIdx.x * blockDim.x + threadIdx.x; t < totalX + totalW;
         t += (size_t)gridDim.x * blockDim.x) {
        if (t < totalX) {
            const size_t u = t;
            const int lane = (int)(u & 31);
            const int k16  = (int)((u >> 5) & 1);
            const int mb   = (int)((u >> 6) & 7);
            const int ck   = (int)((u >> 9) & 63);
            const int mblk = (int)(u >> 15);                 // 0..63
            const int row  = mblk * 128 + mb * 16 + (lane >> 2);
            const int k    = ck * 32 + k16 * 16 + (lane & 3) * 2;
            const float* src = (k < DIMV) ? (x + k) : (h + k - DIMV);
            const size_t r0 = (size_t)row * DIMV, r8 = (size_t)(row + 8) * DIMV;
            uint4 o;
            o.x = packh2(src[r0],     src[r0 + 1]);
            o.y = packh2(src[r8],     src[r8 + 1]);
            o.z = packh2(src[r0 + 8], src[r0 + 9]);
            o.w = packh2(src[r8 + 8], src[r8 + 9]);
            ((uint4*)g_Xh)[u] = o;
        } else {
            const size_t u = t - totalX;
            const int lane = (int)(u & 31);
            const int k16  = (int)((u >> 5) & 1);
            const int n8   = (int)((u >> 6) & 3);
            const int ck   = (int)((u >> 8) & 63);
            const int nblk = (int)((u >> 14) & 31);
            const int g    = (int)(u >> 19);                 // 0..3
            const float* W = (g == 0) ? WI : (g == 1) ? WF : (g == 2) ? WG : WO;
            const int n = nblk * 32 + n8 * 8 + (lane >> 2);
            const int k = ck * 32 + k16 * 16 + (lane & 3) * 2;
            uint2 o;
            o.x = packh2(W[(size_t)k * DIMV + n],       W[(size_t)(k + 1) * DIMV + n]);
            o.y = packh2(W[(size_t)(k + 8) * DIMV + n], W[(size_t)(k + 9) * DIMV + n]);
            ((uint2*)g_Wh)[u] = o;
        }
    }
}

// compile-time per-ks offsets inside a 64-K stage
#define A_OFF(ks) ((uint32_t)(((ks) >> 1) * 8192 + ((ks) & 1) * 512))
#define B_OFF(ks) ((uint32_t)(((ks) >> 1) * 2048 + ((ks) & 1) * 256))

// ---------------- fused GEMM + LSTM kernel ----------------
__global__ void __launch_bounds__(NTHREADS, 2) lstm_mma_kernel(
    const float* __restrict__ c,
    const float* __restrict__ bI, const float* __restrict__ bF,
    const float* __restrict__ bG, const float* __restrict__ bO,
    float* __restrict__ out_h, float* __restrict__ out_c)
{
    extern __shared__ __align__(16) char smem[];
    const uint32_t sbase = smem_u32(smem);
    const int tid  = threadIdx.x;
    const int lane = tid & 31;
    const int wid  = tid >> 5;
    const int nt    = blockIdx.x & (NTILES - 1);   // n fastest -> weights stay L2-resident
    const int mtile = blockIdx.x >> 5;
    const int m0 = mtile * MT;
    const int n0 = nt * NTG;

    // stage biases (128 floats) past the pipeline stages
    if (tid < 4 * NTG) {
        int g = tid >> 5, j = tid & 31;
        const float* bsrc = (g == 0) ? bI : (g == 1) ? bF : (g == 2) ? bG : bO;
        ((float*)(smem + SM_BIAS_B))[tid] = bsrc[n0 + j];
    }

    // ---- stage loader: 2048 16B chunks (1024 A + 1024 B); 8 cp16/thread ----
    auto loadStage = [&](int ckp, int s) {
        const uint32_t As = sbase + (uint32_t)(s * STAGE_B);
        const uint32_t Bs = As + A_TILE_B;
        const char* Asrc = (const char*)g_Xh + ((size_t)mtile * 64 + (size_t)ckp * 2) * 8192;
        #pragma unroll
        for (int r = 0; r < 4; r++) {
            int i = r * NTHREADS + tid;
            cp16(As + (uint32_t)i * 16, Asrc + (size_t)i * 16);
        }
        #pragma unroll
        for (int r = 0; r < 4; r++) {
            int i = r * NTHREADS + tid;
            int g = i >> 8, w = i & 255;
            cp16(Bs + (uint32_t)i * 16,
                 (const char*)g_Wh + (((size_t)g * 32 + nt) * 64 + (size_t)ckp * 2) * 2048
                                   + (size_t)w * 16);
        }
        asm volatile("cp.async.commit_group;" ::: "memory");
    };

    loadStage(0, 0);
    loadStage(1, 1);

    const int wm = wid & 1;     // 2 warps in M (64 rows each)
    const int wn = wid >> 1;    // 4 warps in N (8 cols per gate each)

    float acc[4][4][4];
    #pragma unroll
    for (int mt = 0; mt < 4; mt++)
        #pragma unroll
        for (int g = 0; g < 4; g++)
            #pragma unroll
            for (int e = 0; e < 4; e++) acc[mt][g][e] = 0.0f;

    const uint32_t a_base = (uint32_t)(wm * 4 * 1024 + lane * 16);        // + A_OFF(ks) + mt*1024
    const uint32_t b_base = (uint32_t)(A_TILE_B + wn * 512 + lane * 8);   // + B_OFF(ks) + g*4096

    for (int ck = 0; ck < NCHUNK; ck++) {
        asm volatile("cp.async.wait_group 1;" ::: "memory");
        __syncthreads();
        if (ck + 2 < NCHUNK) loadStage(ck + 2, (ck + 2) % STAGES);
        else asm volatile("cp.async.commit_group;" ::: "memory");

        const uint32_t stg = sbase + (uint32_t)((ck % STAGES) * STAGE_B);

        // ---- ks-level software pipeline: LDS(ks+1) issued before MMA(ks) ----
        uint32_t a[2][4][4], b[2][4][2];
        #pragma unroll
        for (int mt = 0; mt < 4; mt++)
            lds128(stg + a_base + A_OFF(0) + mt * 1024, a[0][mt]);
        #pragma unroll
        for (int g = 0; g < 4; g++)
            lds64(stg + b_base + B_OFF(0) + g * 4096, b[0][g]);

        #pragma unroll
        for (int ks = 0; ks < 4; ks++) {
            const int cur = ks & 1, nxt = cur ^ 1;
            if (ks < 3) {
                const uint32_t ka = (ks == 0) ? A_OFF(1) : (ks == 1) ? A_OFF(2) : A_OFF(3);
                const uint32_t kb = (ks == 0) ? B_OFF(1) : (ks == 1) ? B_OFF(2) : B_OFF(3);
                #pragma unroll
                for (int mt = 0; mt < 4; mt++)
                    lds128(stg + a_base + ka + mt * 1024, a[nxt][mt]);
                #pragma unroll
                for (int g = 0; g < 4; g++)
                    lds64(stg + b_base + kb + g * 4096, b[nxt][g]);
            }
            #pragma unroll
            for (int mt = 0; mt < 4; mt++)
                #pragma unroll
                for (int g = 0; g < 4; g++)
                    mma_f16(acc[mt][g], a[cur][mt], b[cur][g]);
        }
    }
    __syncthreads();

    // ---- fused LSTM epilogue ----
    const float* bias = (const float*)(smem + SM_BIAS_B);
    #pragma unroll
    for (int mt = 0; mt < 4; mt++) {
        #pragma unroll
        for (int er = 0; er < 2; er++) {
            const int m = m0 + wm * 64 + mt * 16 + (lane >> 2) + er * 8;
            const int nl = wn * 8 + 2 * (lane & 3);
            const size_t off = (size_t)m * DIMV + n0 + nl;
            const float2 cv = *(const float2*)(c + off);
            float2 hh, CC;
            #pragma unroll
            for (int cc = 0; cc < 2; cc++) {
                const int e = er * 2 + cc;
                float iv = acc[mt][0][e] + bias[0 * NTG + nl + cc];
                float fv = acc[mt][1][e] + bias[1 * NTG + nl + cc];
                float gv = acc[mt][2][e] + bias[2 * NTG + nl + cc];
                float ov = acc[mt][3][e] + bias[3 * NTG + nl + cc];
                float I = sigm(iv);
                float F = sigm(fv);
                float G = tanhf(gv);
                float O = sigm(ov);
                float Cv = F * (cc ? cv.y : cv.x) + I * G;
                float Hv = O * tanhf(Cv);
                if (cc) { hh.y = Hv; CC.y = Cv; } else { hh.x = Hv; CC.x = Cv; }
            }
            *(float2*)(out_h + off) = hh;
            *(float2*)(out_c + off) = CC;
        }
    }
}

// ---------------- launch ----------------
extern "C" void kernel_launch(void* const* d_in, const int* in_sizes, int n_in,
                              void* d_out, int out_size) {
    (void)in_sizes; (void)n_in; (void)out_size;
    const float* x  = (const float*)d_in[0];
    const float* h  = (const float*)d_in[1];
    const float* c  = (const float*)d_in[2];
    const float* WI = (const float*)d_in[3];
    const float* bI = (const float*)d_in[4];
    const float* WF = (const float*)d_in[5];
    const float* bF = (const float*)d_in[6];
    const float* WG = (const float*)d_in[7];
    const float* bG = (const float*)d_in[8];
    const float* WO = (const float*)d_in[9];
    const float* bO = (const float*)d_in[10];
    float* out_h = (float*)d_out;
    float* out_c = out_h + (size_t)BATCH * DIMV;

    prep_all<<<3072, 256>>>(x, h, WI, WF, WG, WO);

    cudaFuncSetAttribute(lstm_mma_kernel,
                         cudaFuncAttributeMaxDynamicSharedMemorySize, SMEM_TOTAL);
    lstm_mma_kernel<<<MTILES * NTILES, NTHREADS, SMEM_TOTAL>>>(
        c, bI, bF, bG, bO, out_h, out_c);
}